// round 1
// baseline (speedup 1.0000x reference)
#include <cuda_runtime.h>
#include <math.h>

#define Hh 4
#define Bb 32
#define Tt 1500
#define Ep 512
#define Du 1024
#define Kk 512
#define Vv 512
#define CHn 64
#define KEXT 576          // 512 enc dims + 64 conv channels
#define XPITCH 68         // smem pitch (floats): mult of 4 for LDS.128, gcd(68,32)=4 -> only 4-way write conflicts
#define SCALING_F 0.044194173824159216f
#define MAXPFX 208

// ---------------- scratch (static device globals; no allocs allowed) ----------------
__device__ float g_prefix[Hh][CHn][MAXPFX];     // per-head per-channel filter prefix sums
__device__ float g_Wext[Hh][KEXT][Kk];          // [Wk ; Watt] fused weights
__device__ float g_q[Hh][Bb][Kk];               // dec_z @ Wq + bq
__device__ float g_e[Hh][Bb][Tt];               // energies
__device__ float g_w[Hh][Bb][Tt];               // softmax weights
__device__ float g_wenc[Hh][Bb][Ep];            // sum_t w[t]*enc[t]
__device__ float g_ctx[Bb][Hh*Vv];              // per-head contexts, concat layout

__device__ __forceinline__ float tanhfast(float x){
    float y; asm("tanh.approx.f32 %0, %1;" : "=f"(y) : "f"(x)); return y;
}

// ---------------- prefix sums of conv filters ----------------
__global__ void k_prefix(const float* __restrict__ c0, const float* __restrict__ c1,
                         const float* __restrict__ c2, const float* __restrict__ c3){
    int tid = threadIdx.x;              // 256 threads: (h, c)
    int h = tid >> 6, c = tid & 63;
    const float* w = (h == 0) ? c0 : (h == 1) ? c1 : (h == 2) ? c2 : c3;
    int af = 25 * (h + 1);              // FILTS*(h+1)//H
    int ksz = 2 * af + 1;
    float s = 0.f;
    g_prefix[h][c][0] = 0.f;
    for (int j = 0; j < ksz; ++j){
        s += w[c * ksz + j];
        g_prefix[h][c][j + 1] = s;
    }
}

// ---------------- build fused weight matrix ----------------
__global__ void k_wext(const float* __restrict__ Wk, const float* __restrict__ Watt){
    int kx = blockIdx.x, h = blockIdx.y, n = threadIdx.x;   // 512 threads
    float v = (kx < Ep) ? Wk[((size_t)(h * Ep + kx)) * Kk + n]
                        : Watt[((size_t)(h * CHn + (kx - Ep))) * Kk + n];
    g_Wext[h][kx][n] = v;
}

// ---------------- q = dec_z @ Wq + bq ----------------
__global__ void k_q(const float* __restrict__ dec_z, const float* __restrict__ Wq,
                    const float* __restrict__ bq){
    int h = blockIdx.x >> 5, b = blockIdx.x & 31;
    int n = threadIdx.x;                 // 512 threads
    __shared__ float zs[Du];
    zs[n]       = dec_z[(size_t)b * Du + n];
    zs[n + 512] = dec_z[(size_t)b * Du + n + 512];
    __syncthreads();
    float acc = bq[h * Kk + n];
    #pragma unroll 8
    for (int d = 0; d < Du; ++d)
        acc += zs[d] * Wq[((size_t)(h * Du + d)) * Kk + n];
    g_q[h][b][n] = acc;
}

// ---------------- main fused energy kernel ----------------
// Block: one head-batch (h,b), 64 consecutive t rows. 512 threads, thread tid owns column n=tid.
// smem: X^T tile [KEXT][XPITCH] (rows transposed so row-pairs pack into f32x2), + e accumulator.
__global__ void __launch_bounds__(512) k_main(
    const float* __restrict__ enc, const int* __restrict__ lens,
    const float* __restrict__ gw, const float* __restrict__ gb)
{
    extern __shared__ float sm[];
    float* Xst = sm;                       // [KEXT][XPITCH]
    float* e_s = sm + KEXT * XPITCH;       // [64]

    const int tile = blockIdx.x;
    const int hb   = blockIdx.y;
    const int h = hb >> 5, b = hb & 31;
    const int t0 = tile * 64;
    const int tid = threadIdx.x;
    const int len = lens[b];
    const float invlen = 1.0f / (float)len;

    // enc part (k rows [0,512)): coalesced global reads, 4-way-conflict transposed smem writes
    for (int i = tid; i < 64 * Ep; i += 512){
        int r = i >> 9, ee = i & 511;
        int t = t0 + r;
        float v = 0.f;
        if (t < Tt) v = enc[((size_t)b * Tt + t) * Ep + ee];
        Xst[ee * XPITCH + r] = v;
    }
    // conv-coef part (k rows [512,576)) via prefix sums
    {
        const int p = 25 * (h + 1);
        const int ksz = 2 * p + 1;
        for (int i = tid; i < 64 * CHn; i += 512){
            int r = i >> 6, c = i & 63;
            int t = t0 + r;
            float v = 0.f;
            if (t < Tt){
                int jlo = p - t;        if (jlo < 0)   jlo = 0;
                int jhi = len - t + p;  if (jhi > ksz) jhi = ksz;
                if (jhi > jlo) v = invlen * (g_prefix[h][c][jhi] - g_prefix[h][c][jlo]);
            }
            Xst[(Ep + c) * XPITCH + r] = v;
        }
    }
    if (tid < 64) e_s[tid] = 0.f;
    const float qv  = g_q[h][b][tid];
    const float gwv = gw[h * Kk + tid];
    __syncthreads();

    const float* Wp = &g_Wext[h][0][0] + tid;
    const int lane = tid & 31;

    #pragma unroll
    for (int chunk = 0; chunk < 2; ++chunk){
        const float* xp = Xst + chunk * 32;
        unsigned long long acc[16];               // 32 rows as 16 f32x2 pairs
        #pragma unroll
        for (int i = 0; i < 16; ++i) acc[i] = 0ull;

        #pragma unroll 2
        for (int k = 0; k < KEXT; ++k){
            float wv = Wp[(size_t)k * Kk];        // coalesced, L2-resident
            unsigned long long ww;
            asm("mov.b64 %0, {%1, %1};" : "=l"(ww) : "f"(wv));
            const float* xk = xp + k * XPITCH;
            #pragma unroll
            for (int j = 0; j < 8; ++j){
                ulonglong2 xv = *(const ulonglong2*)(xk + 4 * j);  // rows 4j..4j+3 (broadcast LDS.128)
                asm("fma.rn.f32x2 %0, %1, %2, %0;" : "+l"(acc[2*j])   : "l"(xv.x), "l"(ww));
                asm("fma.rn.f32x2 %0, %1, %2, %0;" : "+l"(acc[2*j+1]) : "l"(xv.y), "l"(ww));
            }
        }

        // epilogue: tanh, weight by gw, reduce over n (lanes then warps via smem atomics)
        #pragma unroll
        for (int j = 0; j < 16; ++j){
            unsigned int ulo, uhi;
            asm("mov.b64 {%0, %1}, %2;" : "=r"(ulo), "=r"(uhi) : "l"(acc[j]));
            float v0 = gwv * tanhfast(__uint_as_float(ulo) + qv);
            float v1 = gwv * tanhfast(__uint_as_float(uhi) + qv);
            #pragma unroll
            for (int off = 16; off; off >>= 1){
                v0 += __shfl_down_sync(0xffffffffu, v0, off);
                v1 += __shfl_down_sync(0xffffffffu, v1, off);
            }
            if (lane == 0){
                atomicAdd(&e_s[chunk * 32 + 2 * j],     v0);
                atomicAdd(&e_s[chunk * 32 + 2 * j + 1], v1);
            }
        }
    }
    __syncthreads();
    if (tid < 64){
        int t = t0 + tid;
        if (t < Tt) g_e[h][b][t] = e_s[tid] + gb[h];
    }
}

// ---------------- masked softmax over t, writes w to scratch + d_out ----------------
__global__ void k_softmax(const int* __restrict__ lens, float* __restrict__ out){
    __shared__ float s[Tt];
    __shared__ float red[33];
    int h = blockIdx.x >> 5, b = blockIdx.x & 31;
    int tid = threadIdx.x;                  // 256 threads
    int lane = tid & 31, warp = tid >> 5;
    int len = lens[b];

    float m = -1e30f;
    for (int t = tid; t < len; t += 256){
        float v = SCALING_F * g_e[h][b][t];
        s[t] = v;
        m = fmaxf(m, v);
    }
    #pragma unroll
    for (int off = 16; off; off >>= 1) m = fmaxf(m, __shfl_xor_sync(0xffffffffu, m, off));
    if (lane == 0) red[warp] = m;
    __syncthreads();
    if (tid == 0){
        float v = red[0];
        #pragma unroll
        for (int i = 1; i < 8; ++i) v = fmaxf(v, red[i]);
        red[32] = v;
    }
    __syncthreads();
    float M = red[32];

    float sum = 0.f;
    for (int t = tid; t < len; t += 256){
        float ev = __expf(s[t] - M);
        s[t] = ev;
        sum += ev;
    }
    #pragma unroll
    for (int off = 16; off; off >>= 1) sum += __shfl_xor_sync(0xffffffffu, sum, off);
    if (lane == 0) red[warp] = sum;
    __syncthreads();
    if (tid == 0){
        float v = 0.f;
        #pragma unroll
        for (int i = 0; i < 8; ++i) v += red[i];
        red[32] = v;
    }
    __syncthreads();
    float inv = 1.0f / red[32];

    size_t base = (size_t)(h * Bb + b) * Tt;
    for (int t = tid; t < Tt; t += 256){
        float w = (t < len) ? s[t] * inv : 0.f;
        g_w[h][b][t] = w;
        out[Bb * Ep + base + t] = w;        // ws region after c region
    }
}

// ---------------- wenc[h,b,:] = sum_t w*enc : enc read ONCE for all 4 heads ----------------
__global__ void k_wenc(const float* __restrict__ enc, const int* __restrict__ lens){
    int b = blockIdx.y;
    int tid = threadIdx.x;                   // 128 threads
    int e = blockIdx.x * 128 + tid;
    int len = lens[b];
    __shared__ float ws[Hh][256];
    float a0 = 0.f, a1 = 0.f, a2 = 0.f, a3 = 0.f;
    for (int tb = 0; tb < len; tb += 256){
        int nt = min(256, len - tb);
        __syncthreads();
        for (int i = tid; i < Hh * 256; i += 128){
            int hh = i >> 8, tt = i & 255;
            ws[hh][tt] = (tt < nt) ? g_w[hh][b][tb + tt] : 0.f;
        }
        __syncthreads();
        #pragma unroll 4
        for (int tt = 0; tt < nt; ++tt){
            float x = enc[((size_t)b * Tt + (tb + tt)) * Ep + e];
            a0 += ws[0][tt] * x; a1 += ws[1][tt] * x;
            a2 += ws[2][tt] * x; a3 += ws[3][tt] * x;
        }
    }
    g_wenc[0][b][e] = a0; g_wenc[1][b][e] = a1;
    g_wenc[2][b][e] = a2; g_wenc[3][b][e] = a3;
}

// ---------------- ctx = wenc @ Wv ----------------
__global__ void k_ctx(const float* __restrict__ Wv){
    int h = blockIdx.x >> 5, b = blockIdx.x & 31;
    int v = threadIdx.x;                      // 512 threads
    __shared__ float xr[Ep];
    xr[v] = g_wenc[h][b][v];
    __syncthreads();
    float acc = 0.f;
    #pragma unroll 8
    for (int e = 0; e < Ep; ++e)
        acc += xr[e] * Wv[((size_t)(h * Ep + e)) * Vv + v];
    g_ctx[b][h * Vv + v] = acc;
}

// ---------------- c = concat(ctx) @ Wo ----------------
__global__ void k_out(const float* __restrict__ Wo, float* __restrict__ out){
    int b = blockIdx.x;
    int n = threadIdx.x;                      // 512 threads
    __shared__ float cr[Hh * Vv];
    for (int i = n; i < Hh * Vv; i += 512) cr[i] = g_ctx[b][i];
    __syncthreads();
    float acc = 0.f;
    #pragma unroll 8
    for (int j = 0; j < Hh * Vv; ++j)
        acc += cr[j] * Wo[(size_t)j * Ep + n];
    out[b * Ep + n] = acc;
}

// ---------------- launch ----------------
extern "C" void kernel_launch(void* const* d_in, const int* in_sizes, int n_in,
                              void* d_out, int out_size) {
    const float* enc   = (const float*)d_in[0];
    const int*   lens  = (const int*)  d_in[1];
    const float* dec_z = (const float*)d_in[2];
    const float* Wq    = (const float*)d_in[3];
    const float* bq    = (const float*)d_in[4];
    const float* Wk    = (const float*)d_in[5];
    const float* Wv    = (const float*)d_in[6];
    const float* gw    = (const float*)d_in[7];
    const float* gb    = (const float*)d_in[8];
    const float* Watt  = (const float*)d_in[9];
    const float* Wo    = (const float*)d_in[10];
    const float* cw0   = (const float*)d_in[11];
    const float* cw1   = (const float*)d_in[12];
    const float* cw2   = (const float*)d_in[13];
    const float* cw3   = (const float*)d_in[14];
    float* out = (float*)d_out;

    const int SMEM_MAIN = (KEXT * XPITCH + 64) * (int)sizeof(float);   // 156,928 B
    cudaFuncSetAttribute(k_main, cudaFuncAttributeMaxDynamicSharedMemorySize, SMEM_MAIN);

    k_prefix<<<1, 256>>>(cw0, cw1, cw2, cw3);
    k_wext<<<dim3(KEXT, Hh), 512>>>(Wk, Watt);
    k_q<<<Hh * Bb, 512>>>(dec_z, Wq, bq);
    k_main<<<dim3((Tt + 63) / 64, Hh * Bb), 512, SMEM_MAIN>>>(enc, lens, gw, gb);
    k_softmax<<<Hh * Bb, 256>>>(lens, out);
    k_wenc<<<dim3(Ep / 128, Bb), 128>>>(enc, lens);
    k_ctx<<<Hh * Bb, 512>>>(Wv);
    k_out<<<Bb, 512>>>(Wo, out);
}

// round 2
// speedup vs baseline: 1.5289x; 1.5289x over previous
#include <cuda_runtime.h>
#include <math.h>

#define Hh 4
#define Bb 32
#define Tt 1500
#define Ep 512
#define Du 1024
#define Kk 512
#define Vv 512
#define CHn 64
#define KEXT 576          // 512 enc dims + 64 conv channels
#define XPITCH 68         // smem pitch (floats): mult of 4 for LDS.128
#define SCALING_F 0.044194173824159216f
#define MAXPFX 208

// ---------------- scratch (static device globals; no allocs allowed) ----------------
__device__ float g_prefix[Hh][CHn][MAXPFX];     // per-head per-channel filter prefix sums
__device__ float g_Wext[Hh][KEXT][Kk];          // [Wk ; Watt] fused weights
__device__ float g_q[Hh][Bb][Kk];               // dec_z @ Wq + bq
__device__ float g_e[Hh][Bb][Tt];               // energies
__device__ float g_w[Hh][Bb][Tt];               // softmax weights
__device__ float g_wenc[Hh][Bb][Ep];            // sum_t w[t]*enc[t]
__device__ float g_ctx[Bb][Hh*Vv];              // per-head contexts, concat layout

__device__ __forceinline__ float tanhfast(float x){
    float y; asm("tanh.approx.f32 %0, %1;" : "=f"(y) : "f"(x)); return y;
}

// ---------------- prefix sums of conv filters ----------------
__global__ void k_prefix(const float* __restrict__ c0, const float* __restrict__ c1,
                         const float* __restrict__ c2, const float* __restrict__ c3){
    int tid = threadIdx.x;              // 256 threads: (h, c)
    int h = tid >> 6, c = tid & 63;
    const float* w = (h == 0) ? c0 : (h == 1) ? c1 : (h == 2) ? c2 : c3;
    int af = 25 * (h + 1);              // FILTS*(h+1)//H
    int ksz = 2 * af + 1;
    float s = 0.f;
    g_prefix[h][c][0] = 0.f;
    for (int j = 0; j < ksz; ++j){
        s += w[c * ksz + j];
        g_prefix[h][c][j + 1] = s;
    }
}

// ---------------- build fused weight matrix ----------------
__global__ void k_wext(const float* __restrict__ Wk, const float* __restrict__ Watt){
    int kx = blockIdx.x, h = blockIdx.y, n = threadIdx.x;   // 512 threads
    float v = (kx < Ep) ? Wk[((size_t)(h * Ep + kx)) * Kk + n]
                        : Watt[((size_t)(h * CHn + (kx - Ep))) * Kk + n];
    g_Wext[h][kx][n] = v;
}

// ---------------- q = dec_z @ Wq + bq ----------------
__global__ void k_q(const float* __restrict__ dec_z, const float* __restrict__ Wq,
                    const float* __restrict__ bq){
    int h = blockIdx.x >> 5, b = blockIdx.x & 31;
    int n = threadIdx.x;                 // 512 threads
    __shared__ float zs[Du];
    zs[n]       = dec_z[(size_t)b * Du + n];
    zs[n + 512] = dec_z[(size_t)b * Du + n + 512];
    __syncthreads();
    float acc = bq[h * Kk + n];
    #pragma unroll 8
    for (int d = 0; d < Du; ++d)
        acc += zs[d] * Wq[((size_t)(h * Du + d)) * Kk + n];
    g_q[h][b][n] = acc;
}

// ---------------- main fused energy kernel ----------------
// Block: one (h,b), 64 consecutive t rows. 512 threads.
// Thread = (rowgroup rg = tid>>8, colpair cp = tid&255): rows rg*32..+31, cols 2cp, 2cp+1.
// Per k: 8 broadcast LDS.128 (32 rows) + 1 LDG.64 (2 W cols) + 32 FFMA2 -> fma-pipe bound.
__global__ void __launch_bounds__(512) k_main(
    const float* __restrict__ enc, const int* __restrict__ lens,
    const float* __restrict__ gw, const float* __restrict__ gb)
{
    extern __shared__ float sm[];
    float* Xst = sm;                       // [KEXT][XPITCH] transposed tile
    float* e_s = sm + KEXT * XPITCH;       // [64]

    const int tile = blockIdx.x;
    const int hb   = blockIdx.y;
    const int h = hb >> 5, b = hb & 31;
    const int t0 = tile * 64;
    const int tid = threadIdx.x;
    const int len = lens[b];
    const float invlen = 1.0f / (float)len;

    // enc part (k rows [0,512)): coalesced global reads, transposed smem writes
    for (int i = tid; i < 64 * Ep; i += 512){
        int r = i >> 9, ee = i & 511;
        int t = t0 + r;
        float v = 0.f;
        if (t < Tt) v = enc[((size_t)b * Tt + t) * Ep + ee];
        Xst[ee * XPITCH + r] = v;
    }
    // conv-coef part (k rows [512,576)) via prefix sums
    {
        const int p = 25 * (h + 1);
        const int ksz = 2 * p + 1;
        for (int i = tid; i < 64 * CHn; i += 512){
            int r = i >> 6, c = i & 63;
            int t = t0 + r;
            float v = 0.f;
            if (t < Tt){
                int jlo = p - t;        if (jlo < 0)   jlo = 0;
                int jhi = len - t + p;  if (jhi > ksz) jhi = ksz;
                if (jhi > jlo) v = invlen * (g_prefix[h][c][jhi] - g_prefix[h][c][jlo]);
            }
            Xst[(Ep + c) * XPITCH + r] = v;
        }
    }
    if (tid < 64) e_s[tid] = 0.f;

    const int rg = tid >> 8;              // rowgroup 0/1
    const int cp = tid & 255;             // colpair -> cols 2cp, 2cp+1
    const int lane = tid & 31;

    const float2 qv  = *(const float2*)&g_q[h][b][2 * cp];
    const float2 gwv = *(const float2*)&gw[h * Kk + 2 * cp];
    __syncthreads();

    const float* Wp = &g_Wext[h][0][0] + 2 * cp;
    const float* xp = Xst + rg * 32;

    unsigned long long accA[16], accB[16];     // rowpairs (2j,2j+1) for col0 / col1
    #pragma unroll
    for (int i = 0; i < 16; ++i){ accA[i] = 0ull; accB[i] = 0ull; }

    #pragma unroll 2
    for (int k = 0; k < KEXT; ++k){
        float2 wv = *(const float2*)(Wp + (size_t)k * Kk);   // coalesced, L2-resident
        unsigned long long w0, w1;
        asm("mov.b64 %0, {%1, %1};" : "=l"(w0) : "f"(wv.x));
        asm("mov.b64 %0, {%1, %1};" : "=l"(w1) : "f"(wv.y));
        const float* xk = xp + k * XPITCH;
        #pragma unroll
        for (int j = 0; j < 8; ++j){
            ulonglong2 xv = *(const ulonglong2*)(xk + 4 * j);  // rows 4j..4j+3, broadcast
            asm("fma.rn.f32x2 %0, %1, %2, %0;" : "+l"(accA[2*j])   : "l"(xv.x), "l"(w0));
            asm("fma.rn.f32x2 %0, %1, %2, %0;" : "+l"(accA[2*j+1]) : "l"(xv.y), "l"(w0));
            asm("fma.rn.f32x2 %0, %1, %2, %0;" : "+l"(accB[2*j])   : "l"(xv.x), "l"(w1));
            asm("fma.rn.f32x2 %0, %1, %2, %0;" : "+l"(accB[2*j+1]) : "l"(xv.y), "l"(w1));
        }
    }

    // epilogue: tanh, weight by gw, reduce over cols (warp lanes cover 64 cols)
    #pragma unroll
    for (int j = 0; j < 16; ++j){            // local rows 2j, 2j+1
        unsigned int aLo, aHi, bLo, bHi;
        asm("mov.b64 {%0, %1}, %2;" : "=r"(aLo), "=r"(aHi) : "l"(accA[j]));
        asm("mov.b64 {%0, %1}, %2;" : "=r"(bLo), "=r"(bHi) : "l"(accB[j]));
        float vlo = gwv.x * tanhfast(__uint_as_float(aLo) + qv.x)
                  + gwv.y * tanhfast(__uint_as_float(bLo) + qv.y);
        float vhi = gwv.x * tanhfast(__uint_as_float(aHi) + qv.x)
                  + gwv.y * tanhfast(__uint_as_float(bHi) + qv.y);
        #pragma unroll
        for (int off = 16; off; off >>= 1){
            vlo += __shfl_down_sync(0xffffffffu, vlo, off);
            vhi += __shfl_down_sync(0xffffffffu, vhi, off);
        }
        if (lane == 0){
            atomicAdd(&e_s[rg * 32 + 2 * j],     vlo);
            atomicAdd(&e_s[rg * 32 + 2 * j + 1], vhi);
        }
    }
    __syncthreads();
    if (tid < 64){
        int t = t0 + tid;
        if (t < Tt) g_e[h][b][t] = e_s[tid] + gb[h];
    }
}

// ---------------- masked softmax over t, writes w to scratch + d_out ----------------
__global__ void k_softmax(const int* __restrict__ lens, float* __restrict__ out){
    __shared__ float s[Tt];
    __shared__ float red[33];
    int h = blockIdx.x >> 5, b = blockIdx.x & 31;
    int tid = threadIdx.x;                  // 256 threads
    int lane = tid & 31, warp = tid >> 5;
    int len = lens[b];

    float m = -1e30f;
    for (int t = tid; t < len; t += 256){
        float v = SCALING_F * g_e[h][b][t];
        s[t] = v;
        m = fmaxf(m, v);
    }
    #pragma unroll
    for (int off = 16; off; off >>= 1) m = fmaxf(m, __shfl_xor_sync(0xffffffffu, m, off));
    if (lane == 0) red[warp] = m;
    __syncthreads();
    if (tid == 0){
        float v = red[0];
        #pragma unroll
        for (int i = 1; i < 8; ++i) v = fmaxf(v, red[i]);
        red[32] = v;
    }
    __syncthreads();
    float M = red[32];

    float sum = 0.f;
    for (int t = tid; t < len; t += 256){
        float ev = __expf(s[t] - M);
        s[t] = ev;
        sum += ev;
    }
    #pragma unroll
    for (int off = 16; off; off >>= 1) sum += __shfl_xor_sync(0xffffffffu, sum, off);
    if (lane == 0) red[warp] = sum;
    __syncthreads();
    if (tid == 0){
        float v = 0.f;
        #pragma unroll
        for (int i = 0; i < 8; ++i) v += red[i];
        red[32] = v;
    }
    __syncthreads();
    float inv = 1.0f / red[32];

    size_t base = (size_t)(h * Bb + b) * Tt;
    for (int t = tid; t < Tt; t += 256){
        float w = (t < len) ? s[t] * inv : 0.f;
        g_w[h][b][t] = w;
        out[Bb * Ep + base + t] = w;        // ws region after c region
    }
}

// ---------------- wenc[h,b,:] = sum_t w*enc : enc read ONCE for all 4 heads ----------------
__global__ void k_wenc(const float* __restrict__ enc, const int* __restrict__ lens){
    int b = blockIdx.y;
    int tid = threadIdx.x;                   // 128 threads
    int e = blockIdx.x * 128 + tid;
    int len = lens[b];
    __shared__ float ws[Hh][256];
    float a0 = 0.f, a1 = 0.f, a2 = 0.f, a3 = 0.f;
    for (int tb = 0; tb < len; tb += 256){
        int nt = min(256, len - tb);
        __syncthreads();
        for (int i = tid; i < Hh * 256; i += 128){
            int hh = i >> 8, tt = i & 255;
            ws[hh][tt] = (tt < nt) ? g_w[hh][b][tb + tt] : 0.f;
        }
        __syncthreads();
        #pragma unroll 4
        for (int tt = 0; tt < nt; ++tt){
            float x = enc[((size_t)b * Tt + (tb + tt)) * Ep + e];
            a0 += ws[0][tt] * x; a1 += ws[1][tt] * x;
            a2 += ws[2][tt] * x; a3 += ws[3][tt] * x;
        }
    }
    g_wenc[0][b][e] = a0; g_wenc[1][b][e] = a1;
    g_wenc[2][b][e] = a2; g_wenc[3][b][e] = a3;
}

// ---------------- ctx = wenc @ Wv ----------------
__global__ void k_ctx(const float* __restrict__ Wv){
    int h = blockIdx.x >> 5, b = blockIdx.x & 31;
    int v = threadIdx.x;                      // 512 threads
    __shared__ float xr[Ep];
    xr[v] = g_wenc[h][b][v];
    __syncthreads();
    float acc = 0.f;
    #pragma unroll 8
    for (int e = 0; e < Ep; ++e)
        acc += xr[e] * Wv[((size_t)(h * Ep + e)) * Vv + v];
    g_ctx[b][h * Vv + v] = acc;
}

// ---------------- c = concat(ctx) @ Wo ----------------
__global__ void k_out(const float* __restrict__ Wo, float* __restrict__ out){
    int b = blockIdx.x;
    int n = threadIdx.x;                      // 512 threads
    __shared__ float cr[Hh * Vv];
    for (int i = n; i < Hh * Vv; i += 512) cr[i] = g_ctx[b][i];
    __syncthreads();
    float acc = 0.f;
    #pragma unroll 8
    for (int j = 0; j < Hh * Vv; ++j)
        acc += cr[j] * Wo[(size_t)j * Ep + n];
    out[b * Ep + n] = acc;
}

// ---------------- launch ----------------
extern "C" void kernel_launch(void* const* d_in, const int* in_sizes, int n_in,
                              void* d_out, int out_size) {
    const float* enc   = (const float*)d_in[0];
    const int*   lens  = (const int*)  d_in[1];
    const float* dec_z = (const float*)d_in[2];
    const float* Wq    = (const float*)d_in[3];
    const float* bq    = (const float*)d_in[4];
    const float* Wk    = (const float*)d_in[5];
    const float* Wv    = (const float*)d_in[6];
    const float* gw    = (const float*)d_in[7];
    const float* gb    = (const float*)d_in[8];
    const float* Watt  = (const float*)d_in[9];
    const float* Wo    = (const float*)d_in[10];
    const float* cw0   = (const float*)d_in[11];
    const float* cw1   = (const float*)d_in[12];
    const float* cw2   = (const float*)d_in[13];
    const float* cw3   = (const float*)d_in[14];
    float* out = (float*)d_out;

    const int SMEM_MAIN = (KEXT * XPITCH + 64) * (int)sizeof(float);   // 156,928 B
    cudaFuncSetAttribute(k_main, cudaFuncAttributeMaxDynamicSharedMemorySize, SMEM_MAIN);

    k_prefix<<<1, 256>>>(cw0, cw1, cw2, cw3);
    k_wext<<<dim3(KEXT, Hh), 512>>>(Wk, Watt);
    k_q<<<Hh * Bb, 512>>>(dec_z, Wq, bq);
    k_main<<<dim3((Tt + 63) / 64, Hh * Bb), 512, SMEM_MAIN>>>(enc, lens, gw, gb);
    k_softmax<<<Hh * Bb, 256>>>(lens, out);
    k_wenc<<<dim3(Ep / 128, Bb), 128>>>(enc, lens);
    k_ctx<<<Hh * Bb, 512>>>(Wv);
    k_out<<<Bb, 512>>>(Wo, out);
}

// round 6
// speedup vs baseline: 4.2317x; 2.7678x over previous
#include <cuda_runtime.h>
#include <cuda_bf16.h>
#include <math.h>
#include <stdint.h>

#define Hh 4
#define Bb 32
#define Tt 1500
#define Ep 512
#define Du 1024
#define Kk 512
#define Vv 512
#define CHn 64
#define KEXT 576
#define SCALING_F 0.044194173824159216f
#define MAXPFX 208
#define NSEG 8
#define SEGLEN 188

#define XP 584            // smem pitch in bf16 halves: 1168B rows, 16B aligned, LDSM conflict-free

// ---------------- static device scratch ----------------
__device__ float g_prefix[Hh][CHn][MAXPFX];
__device__ float g_q[Hh][Bb][Kk];
__device__ float g_e[Hh][Bb][Tt];
__device__ float g_w[Hh][Bb][Tt];
__device__ float g_wpart[NSEG][Hh][Bb][Ep];
__device__ float g_wenc[Hh][Bb][Ep];
__device__ float g_ctx[Bb][Hh*Vv];
__device__ uint4 g_encbf4[(size_t)Bb*Tt*Ep/8];        // [b][t][k<512] bf16
__device__ uint4 g_convbf4[(size_t)Hh*Bb*Tt*CHn/8];   // [h][b][t][c]  bf16
__device__ uint4 g_wt4[(size_t)Hh*Kk*KEXT/8];         // [h][n][k]     bf16 (W^T)

__device__ __forceinline__ float tanhfast(float x){
    float y; asm("tanh.approx.f32 %0, %1;" : "=f"(y) : "f"(x)); return y;
}
__device__ __forceinline__ uint32_t smem_u32(const void* p){
    uint32_t a; asm("{ .reg .u64 t; cvta.to.shared.u64 t, %1; cvt.u32.u64 %0, t; }" : "=r"(a) : "l"(p));
    return a;
}
__device__ __forceinline__ void ldsm4(uint32_t& r0, uint32_t& r1, uint32_t& r2, uint32_t& r3,
                                      uint32_t addr){
    asm volatile("ldmatrix.sync.aligned.m8n8.x4.shared.b16 {%0,%1,%2,%3}, [%4];"
                 : "=r"(r0), "=r"(r1), "=r"(r2), "=r"(r3) : "r"(addr));
}
__device__ __forceinline__ void mma_bf16(float& c0, float& c1, float& c2, float& c3,
                                         uint32_t a0, uint32_t a1, uint32_t a2, uint32_t a3,
                                         uint32_t b0, uint32_t b1){
    asm volatile("mma.sync.aligned.m16n8k16.row.col.f32.bf16.bf16.f32 "
                 "{%0,%1,%2,%3}, {%4,%5,%6,%7}, {%8,%9}, {%0,%1,%2,%3};"
                 : "+f"(c0), "+f"(c1), "+f"(c2), "+f"(c3)
                 : "r"(a0), "r"(a1), "r"(a2), "r"(a3), "r"(b0), "r"(b1));
}
__device__ __forceinline__ void cp16(uint32_t dst, const void* src){
    asm volatile("cp.async.cg.shared.global [%0], [%1], 16;" :: "r"(dst), "l"(src) : "memory");
}
__device__ __forceinline__ void cp_commit(){ asm volatile("cp.async.commit_group;" ::: "memory"); }
__device__ __forceinline__ void cp_wait0(){ asm volatile("cp.async.wait_group 0;" ::: "memory"); }

// ---------------- prefix sums of conv filters ----------------
__global__ void k_prefix(const float* __restrict__ c0, const float* __restrict__ c1,
                         const float* __restrict__ c2, const float* __restrict__ c3){
    int tid = threadIdx.x;
    int h = tid >> 6, c = tid & 63;
    const float* w = (h == 0) ? c0 : (h == 1) ? c1 : (h == 2) ? c2 : c3;
    int af = 25 * (h + 1);
    int ksz = 2 * af + 1;
    float s = 0.f;
    g_prefix[h][c][0] = 0.f;
    for (int j = 0; j < ksz; ++j){
        s += w[c * ksz + j];
        g_prefix[h][c][j + 1] = s;
    }
}

// ---------------- enc fp32 -> bf16 ----------------
__global__ void k_prep_enc(const float* __restrict__ enc){
    int i = blockIdx.x * 256 + threadIdx.x;
    const int N4 = Bb * Tt * Ep / 8;
    if (i >= N4) return;
    const float4* src = (const float4*)enc;
    float4 a = src[2 * i], b = src[2 * i + 1];
    __nv_bfloat162 p0 = __floats2bfloat162_rn(a.x, a.y);
    __nv_bfloat162 p1 = __floats2bfloat162_rn(a.z, a.w);
    __nv_bfloat162 p2 = __floats2bfloat162_rn(b.x, b.y);
    __nv_bfloat162 p3 = __floats2bfloat162_rn(b.z, b.w);
    uint4 v;
    v.x = *(uint32_t*)&p0; v.y = *(uint32_t*)&p1;
    v.z = *(uint32_t*)&p2; v.w = *(uint32_t*)&p3;
    g_encbf4[i] = v;
}

// ---------------- conv coefficients -> bf16 ----------------
__global__ void k_prep_conv(const int* __restrict__ lens){
    int idx = blockIdx.x * 1024 + threadIdx.x;
    const int N = Hh * Bb * Tt * CHn;
    if (idx >= N) return;
    int c = idx & 63;
    int t = (idx >> 6) % Tt;
    int hb = idx / (64 * Tt);
    int b = hb & 31, h = hb >> 5;
    int len = lens[b];
    int p = 25 * (h + 1);
    int ksz = 2 * p + 1;
    float v = 0.f;
    int jlo = p - t;        if (jlo < 0)   jlo = 0;
    int jhi = len - t + p;  if (jhi > ksz) jhi = ksz;
    if (jhi > jlo) v = (g_prefix[h][c][jhi] - g_prefix[h][c][jlo]) / (float)len;
    ((__nv_bfloat16*)g_convbf4)[idx] = __float2bfloat16_rn(v);
}

// ---------------- W^T bf16: g_wt[h][n][k] ----------------
__global__ void k_prep_w(const float* __restrict__ Wk, const float* __restrict__ Watt){
    int idx = blockIdx.x * 1024 + threadIdx.x;
    const int N = Hh * Kk * KEXT;
    if (idx >= N) return;
    int kx = idx % KEXT;
    int r  = idx / KEXT;
    int n = r % Kk, h = r / Kk;
    float v = (kx < Ep) ? Wk[((size_t)(h * Ep + kx)) * Kk + n]
                        : Watt[((size_t)(h * CHn + (kx - Ep))) * Kk + n];
    ((__nv_bfloat16*)g_wt4)[idx] = __float2bfloat16_rn(v);
}

// ---------------- q = dec_z @ Wq + bq ----------------
__global__ void k_q(const float* __restrict__ dec_z, const float* __restrict__ Wq,
                    const float* __restrict__ bq){
    int h = blockIdx.x >> 5, b = blockIdx.x & 31;
    int n = threadIdx.x;
    __shared__ float zs[Du];
    zs[n]       = dec_z[(size_t)b * Du + n];
    zs[n + 512] = dec_z[(size_t)b * Du + n + 512];
    __syncthreads();
    float acc = bq[h * Kk + n];
    #pragma unroll 8
    for (int d = 0; d < Du; ++d)
        acc += zs[d] * Wq[((size_t)(h * Du + d)) * Kk + n];
    g_q[h][b][n] = acc;
}

// ---------------- HMMA energy GEMM (double-buffered W via cp.async) ----------------
// Block = (t-tile of 128, h*32+b). 256 threads / 8 warps, warp w owns rows w*16..+15.
// X[128x576]bf16 resident; 16 n-chunks of 32: prefetch chunk s+1 while MMAing chunk s.
#define SM_X   0
#define SM_W0  149504                  // 128*XP*2
#define SM_W1  186880                  // + 32*XP*2
#define SM_Q   224256                  // + 32*XP*2
#define SM_GW  226304
#define SMEM_MMA 228352

__global__ void __launch_bounds__(256) k_mma(const float* __restrict__ gw,
                                             const float* __restrict__ gb){
    extern __shared__ char sm[];
    const uint32_t smb = smem_u32(sm);
    const int tid = threadIdx.x;
    const int wid = tid >> 5, lane = tid & 31;
    const int t0 = blockIdx.x * 128;
    const int hb = blockIdx.y;
    const int h = hb >> 5, b = hb & 31;
    const int gid = lane >> 2, tig = lane & 3;

    // ---- prefetch W chunk 0 first (overlaps with X fill) ----
    for (int i = tid; i < 32 * 72; i += 256){
        int r = i / 72, g = i % 72;
        cp16(smb + SM_W0 + r * (XP * 2) + g * 16,
             &g_wt4[((size_t)(h * Kk + r) * KEXT) / 8 + g]);
    }
    cp_commit();

    // ---- fill X: 128 rows x 72 uint4 (576 halves) ----
    for (int i = tid; i < 128 * 72; i += 256){
        int r = i / 72, g = i % 72;
        int t = t0 + r;
        uint4 v = make_uint4(0u, 0u, 0u, 0u);
        if (t < Tt){
            v = (g < 64) ? g_encbf4[(size_t)(b * Tt + t) * 64 + g]
                         : g_convbf4[(size_t)((h * Bb + b) * Tt + t) * 8 + (g - 64)];
        }
        *(uint4*)(sm + SM_X + r * (XP * 2) + g * 16) = v;
    }
    for (int i = tid; i < 512; i += 256){
        ((float*)(sm + SM_Q))[i]  = g_q[h][b][i];
        ((float*)(sm + SM_GW))[i] = gw[h * Kk + i];
    }

    // ldmatrix lane address bases
    const uint32_t aBase = smb + SM_X
        + (uint32_t)(wid * 16 + (lane & 7) + ((lane >> 3) & 1) * 8) * (XP * 2)
        + (uint32_t)(lane >> 4) * 16;
    const uint32_t bOff = (uint32_t)((lane & 7) + (lane >> 4) * 8) * (XP * 2)
                        + (uint32_t)((lane >> 3) & 1) * 16;

    float epart0 = 0.f, epart1 = 0.f;      // rows wid*16+gid, +8
    const float* qs = (const float*)(sm + SM_Q);
    const float* gs = (const float*)(sm + SM_GW);

    for (int s = 0; s < 16; ++s){
        const uint32_t wCur = (s & 1) ? (smb + SM_W1) : (smb + SM_W0);
        const uint32_t wNxt = (s & 1) ? (smb + SM_W0) : (smb + SM_W1);

        cp_wait0();
        __syncthreads();                    // chunk s resident; prior readers of wNxt done

        if (s < 15){
            for (int i = tid; i < 32 * 72; i += 256){
                int r = i / 72, g = i % 72;
                cp16(wNxt + r * (XP * 2) + g * 16,
                     &g_wt4[((size_t)(h * Kk + (s + 1) * 32 + r) * KEXT) / 8 + g]);
            }
            cp_commit();
        }

        float acc[16];
        #pragma unroll
        for (int i = 0; i < 16; ++i) acc[i] = 0.f;

        #pragma unroll 4
        for (int ks = 0; ks < 36; ++ks){
            uint32_t a0, a1, a2, a3;
            ldsm4(a0, a1, a2, a3, aBase + ks * 32);
            #pragma unroll
            for (int p = 0; p < 2; ++p){
                uint32_t b0, b1, b2, b3;
                ldsm4(b0, b1, b2, b3, wCur + (uint32_t)p * 16 * (XP * 2) + bOff + ks * 32);
                mma_bf16(acc[p*8+0], acc[p*8+1], acc[p*8+2], acc[p*8+3], a0, a1, a2, a3, b0, b1);
                mma_bf16(acc[p*8+4], acc[p*8+5], acc[p*8+6], acc[p*8+7], a0, a1, a2, a3, b2, b3);
            }
        }

        // epilogue for this 32-col chunk
        #pragma unroll
        for (int j = 0; j < 4; ++j){
            int n = s * 32 + j * 8 + tig * 2;
            float2 qv = *(const float2*)(qs + n);
            float2 gv = *(const float2*)(gs + n);
            epart0 += gv.x * tanhfast(acc[j*4+0] + qv.x) + gv.y * tanhfast(acc[j*4+1] + qv.y);
            epart1 += gv.x * tanhfast(acc[j*4+2] + qv.x) + gv.y * tanhfast(acc[j*4+3] + qv.y);
        }
        __syncthreads();                    // all warps done reading wCur before s+1 overwrites it
    }

    // reduce over tig (4 lanes per row) via xor shuffles within quad
    #pragma unroll
    for (int off = 1; off < 4; off <<= 1){
        epart0 += __shfl_xor_sync(0xffffffffu, epart0, off);
        epart1 += __shfl_xor_sync(0xffffffffu, epart1, off);
    }
    if (tig == 0){
        float gbv = gb[h];
        int r0 = wid * 16 + gid;
        int t_a = t0 + r0, t_b = t0 + r0 + 8;
        if (t_a < Tt) g_e[h][b][t_a] = epart0 + gbv;
        if (t_b < Tt) g_e[h][b][t_b] = epart1 + gbv;
    }
}

// ---------------- masked softmax over t ----------------
__global__ void k_softmax(const int* __restrict__ lens, float* __restrict__ out){
    __shared__ float s[Tt];
    __shared__ float red[33];
    int h = blockIdx.x >> 5, b = blockIdx.x & 31;
    int tid = threadIdx.x;
    int lane = tid & 31, warp = tid >> 5;
    int len = lens[b];

    float m = -1e30f;
    for (int t = tid; t < len; t += 256){
        float v = SCALING_F * g_e[h][b][t];
        s[t] = v;
        m = fmaxf(m, v);
    }
    #pragma unroll
    for (int off = 16; off; off >>= 1) m = fmaxf(m, __shfl_xor_sync(0xffffffffu, m, off));
    if (lane == 0) red[warp] = m;
    __syncthreads();
    if (tid == 0){
        float v = red[0];
        #pragma unroll
        for (int i = 1; i < 8; ++i) v = fmaxf(v, red[i]);
        red[32] = v;
    }
    __syncthreads();
    float M = red[32];

    float sum = 0.f;
    for (int t = tid; t < len; t += 256){
        float ev = __expf(s[t] - M);
        s[t] = ev;
        sum += ev;
    }
    #pragma unroll
    for (int off = 16; off; off >>= 1) sum += __shfl_xor_sync(0xffffffffu, sum, off);
    if (lane == 0) red[warp] = sum;
    __syncthreads();
    if (tid == 0){
        float v = 0.f;
        #pragma unroll
        for (int i = 0; i < 8; ++i) v += red[i];
        red[32] = v;
    }
    __syncthreads();
    float inv = 1.0f / red[32];

    size_t base = (size_t)(h * Bb + b) * Tt;
    for (int t = tid; t < Tt; t += 256){
        float w = (t < len) ? s[t] * inv : 0.f;
        g_w[h][b][t] = w;
        out[Bb * Ep + base + t] = w;
    }
}

// ---------------- wenc phase 1: t-segment partials (deterministic) ----------------
__global__ void k_wenc1(const float* __restrict__ enc, const int* __restrict__ lens){
    int seg = blockIdx.x, b = blockIdx.y;
    int e = threadIdx.x;
    int len = lens[b];
    int tstart = seg * SEGLEN;
    int tend = min(tstart + SEGLEN, len);
    int nt = tend - tstart; if (nt < 0) nt = 0;
    __shared__ float ws[Hh][SEGLEN];
    for (int i = e; i < Hh * SEGLEN; i += 512){
        int hh = i / SEGLEN, tt = i % SEGLEN;
        ws[hh][tt] = (tt < nt) ? g_w[hh][b][tstart + tt] : 0.f;
    }
    __syncthreads();
    float a0 = 0.f, a1 = 0.f, a2 = 0.f, a3 = 0.f;
    for (int tt = 0; tt < nt; ++tt){
        float x = enc[((size_t)b * Tt + (tstart + tt)) * Ep + e];
        a0 += ws[0][tt] * x; a1 += ws[1][tt] * x;
        a2 += ws[2][tt] * x; a3 += ws[3][tt] * x;
    }
    g_wpart[seg][0][b][e] = a0; g_wpart[seg][1][b][e] = a1;
    g_wpart[seg][2][b][e] = a2; g_wpart[seg][3][b][e] = a3;
}

// ---------------- wenc phase 2: reduce segments ----------------
__global__ void k_wenc2(){
    int b = blockIdx.x;
    int e = threadIdx.x;
    #pragma unroll
    for (int hh = 0; hh < Hh; ++hh){
        float a = 0.f;
        #pragma unroll
        for (int s = 0; s < NSEG; ++s) a += g_wpart[s][hh][b][e];
        g_wenc[hh][b][e] = a;
    }
}

// ---------------- ctx = wenc @ Wv ----------------
__global__ void k_ctx(const float* __restrict__ Wv){
    int h = blockIdx.x >> 5, b = blockIdx.x & 31;
    int v = threadIdx.x;
    __shared__ float xr[Ep];
    xr[v] = g_wenc[h][b][v];
    __syncthreads();
    float acc = 0.f;
    #pragma unroll 8
    for (int e = 0; e < Ep; ++e)
        acc += xr[e] * Wv[((size_t)(h * Ep + e)) * Vv + v];
    g_ctx[b][h * Vv + v] = acc;
}

// ---------------- c = concat(ctx) @ Wo ----------------
__global__ void k_out(const float* __restrict__ Wo, float* __restrict__ out){
    int b = blockIdx.x;
    int n = threadIdx.x;
    __shared__ float cr[Hh * Vv];
    for (int i = n; i < Hh * Vv; i += 512) cr[i] = g_ctx[b][i];
    __syncthreads();
    float acc = 0.f;
    #pragma unroll 8
    for (int j = 0; j < Hh * Vv; ++j)
        acc += cr[j] * Wo[(size_t)j * Ep + n];
    out[b * Ep + n] = acc;
}

// ---------------- launch ----------------
extern "C" void kernel_launch(void* const* d_in, const int* in_sizes, int n_in,
                              void* d_out, int out_size) {
    const float* enc   = (const float*)d_in[0];
    const int*   lens  = (const int*)  d_in[1];
    const float* dec_z = (const float*)d_in[2];
    const float* Wq    = (const float*)d_in[3];
    const float* bq    = (const float*)d_in[4];
    const float* Wk    = (const float*)d_in[5];
    const float* Wv    = (const float*)d_in[6];
    const float* gw    = (const float*)d_in[7];
    const float* gb    = (const float*)d_in[8];
    const float* Watt  = (const float*)d_in[9];
    const float* Wo    = (const float*)d_in[10];
    const float* cw0   = (const float*)d_in[11];
    const float* cw1   = (const float*)d_in[12];
    const float* cw2   = (const float*)d_in[13];
    const float* cw3   = (const float*)d_in[14];
    float* out = (float*)d_out;

    cudaFuncSetAttribute(k_mma, cudaFuncAttributeMaxDynamicSharedMemorySize, SMEM_MMA);

    k_prefix<<<1, 256>>>(cw0, cw1, cw2, cw3);
    k_prep_enc<<<(Bb * Tt * Ep / 8 + 255) / 256, 256>>>(enc);
    k_prep_conv<<<(Hh * Bb * Tt * CHn + 1023) / 1024, 1024>>>(lens);
    k_prep_w<<<(Hh * Kk * KEXT + 1023) / 1024, 1024>>>(Wk, Watt);
    k_q<<<Hh * Bb, 512>>>(dec_z, Wq, bq);
    k_mma<<<dim3((Tt + 127) / 128, Hh * Bb), 256, SMEM_MMA>>>(gw, gb);
    k_softmax<<<Hh * Bb, 256>>>(lens, out);
    k_wenc1<<<dim3(NSEG, Bb), 512>>>(enc, lens);
    k_wenc2<<<Bb, 512>>>();
    k_ctx<<<Hh * Bb, 512>>>(Wv);
    k_out<<<Bb, 512>>>(Wo, out);
}

// round 8
// speedup vs baseline: 4.8321x; 1.1419x over previous
#include <cuda_runtime.h>
#include <cuda_bf16.h>
#include <math.h>
#include <stdint.h>

#define Hh 4
#define Bb 32
#define Tt 1500
#define Ep 512
#define Du 1024
#define Kk 512
#define Vv 512
#define CHn 64
#define KEXT 576
#define SCALING_F 0.044194173824159216f
#define MAXPFX 208
#define NSEG 8
#define SEGLEN 188

#define XP 584            // smem pitch in bf16 halves: 1168B rows, 16B aligned, LDSM conflict-free

// ---------------- static device scratch ----------------
__device__ float g_prefixT[Hh][MAXPFX][CHn];          // transposed: [h][j][c], c contiguous
__device__ float g_q[Hh][Bb][Kk];
__device__ float g_e[Hh][Bb][Tt];
__device__ float g_w[Hh][Bb][Tt];
__device__ float g_wpart[NSEG][Hh][Bb][Ep];
__device__ float g_wenc[Hh][Bb][Ep];
__device__ float g_ctx[Bb][Hh*Vv];
__device__ uint4 g_encbf4[(size_t)Bb*Tt*Ep/8];        // [b][t][k<512] bf16
__device__ uint4 g_wt4[(size_t)Hh*Kk*KEXT/8];         // [h][n][k]     bf16 (W^T)

__device__ __forceinline__ float tanhfast(float x){
    float y; asm("tanh.approx.f32 %0, %1;" : "=f"(y) : "f"(x)); return y;
}
__device__ __forceinline__ uint32_t smem_u32(const void* p){
    uint32_t a; asm("{ .reg .u64 t; cvta.to.shared.u64 t, %1; cvt.u32.u64 %0, t; }" : "=r"(a) : "l"(p));
    return a;
}
__device__ __forceinline__ void ldsm4(uint32_t& r0, uint32_t& r1, uint32_t& r2, uint32_t& r3,
                                      uint32_t addr){
    asm volatile("ldmatrix.sync.aligned.m8n8.x4.shared.b16 {%0,%1,%2,%3}, [%4];"
                 : "=r"(r0), "=r"(r1), "=r"(r2), "=r"(r3) : "r"(addr));
}
__device__ __forceinline__ void mma_bf16(float& c0, float& c1, float& c2, float& c3,
                                         uint32_t a0, uint32_t a1, uint32_t a2, uint32_t a3,
                                         uint32_t b0, uint32_t b1){
    asm volatile("mma.sync.aligned.m16n8k16.row.col.f32.bf16.bf16.f32 "
                 "{%0,%1,%2,%3}, {%4,%5,%6,%7}, {%8,%9}, {%0,%1,%2,%3};"
                 : "+f"(c0), "+f"(c1), "+f"(c2), "+f"(c3)
                 : "r"(a0), "r"(a1), "r"(a2), "r"(a3), "r"(b0), "r"(b1));
}
__device__ __forceinline__ void cp16(uint32_t dst, const void* src){
    asm volatile("cp.async.cg.shared.global [%0], [%1], 16;" :: "r"(dst), "l"(src) : "memory");
}
__device__ __forceinline__ void cp_commit(){ asm volatile("cp.async.commit_group;" ::: "memory"); }
__device__ __forceinline__ void cp_wait0(){ asm volatile("cp.async.wait_group 0;" ::: "memory"); }

// ---------------- enc fp32 -> bf16 ----------------
__global__ void k_prep_enc(const float* __restrict__ enc){
    int i = blockIdx.x * 256 + threadIdx.x;
    const int N4 = Bb * Tt * Ep / 8;
    if (i >= N4) return;
    const float4* src = (const float4*)enc;
    float4 a = src[2 * i], b = src[2 * i + 1];
    __nv_bfloat162 p0 = __floats2bfloat162_rn(a.x, a.y);
    __nv_bfloat162 p1 = __floats2bfloat162_rn(a.z, a.w);
    __nv_bfloat162 p2 = __floats2bfloat162_rn(b.x, b.y);
    __nv_bfloat162 p3 = __floats2bfloat162_rn(b.z, b.w);
    uint4 v;
    v.x = *(uint32_t*)&p0; v.y = *(uint32_t*)&p1;
    v.z = *(uint32_t*)&p2; v.w = *(uint32_t*)&p3;
    g_encbf4[i] = v;
}

// ---------------- W^T bf16: g_wt[h][n][k] ----------------
__global__ void k_prep_w(const float* __restrict__ Wk, const float* __restrict__ Watt){
    int idx = blockIdx.x * 1024 + threadIdx.x;
    const int N = Hh * Kk * KEXT;
    if (idx >= N) return;
    int kx = idx % KEXT;
    int r  = idx / KEXT;
    int n = r % Kk, h = r / Kk;
    float v = (kx < Ep) ? Wk[((size_t)(h * Ep + kx)) * Kk + n]
                        : Watt[((size_t)(h * CHn + (kx - Ep))) * Kk + n];
    ((__nv_bfloat16*)g_wt4)[idx] = __float2bfloat16_rn(v);
}

// ---------------- q = dec_z @ Wq + bq   (+ block 128: filter prefix sums) ----------------
__global__ void k_qp(const float* __restrict__ dec_z, const float* __restrict__ Wq,
                     const float* __restrict__ bq,
                     const float* __restrict__ c0, const float* __restrict__ c1,
                     const float* __restrict__ c2, const float* __restrict__ c3){
    if (blockIdx.x == Hh * Bb){
        int tid = threadIdx.x;
        if (tid < Hh * CHn){
            int h = tid >> 6, c = tid & 63;
            const float* w = (h == 0) ? c0 : (h == 1) ? c1 : (h == 2) ? c2 : c3;
            int af = 25 * (h + 1);
            int ksz = 2 * af + 1;
            float s = 0.f;
            g_prefixT[h][0][c] = 0.f;
            for (int j = 0; j < ksz; ++j){
                s += w[c * ksz + j];
                g_prefixT[h][j + 1][c] = s;
            }
        }
        return;
    }
    int h = blockIdx.x >> 5, b = blockIdx.x & 31;
    int n = threadIdx.x;
    __shared__ float zs[Du];
    zs[n]       = dec_z[(size_t)b * Du + n];
    zs[n + 512] = dec_z[(size_t)b * Du + n + 512];
    __syncthreads();
    float acc = bq[h * Kk + n];
    #pragma unroll 8
    for (int d = 0; d < Du; ++d)
        acc += zs[d] * Wq[((size_t)(h * Du + d)) * Kk + n];
    g_q[h][b][n] = acc;
}

// ---------------- HMMA energy GEMM (double-buffered W via cp.async, conv folded) ----------------
// Block = (t-tile of 128, h*32+b). 256 threads / 8 warps, warp w owns rows w*16..+15.
// X[128x576]bf16 resident; 16 n-chunks of 32: prefetch chunk s+1 while MMAing chunk s.
#define SM_X   0
#define SM_W0  149504                  // 128*XP*2
#define SM_W1  186880                  // + 32*XP*2
#define SM_Q   224256                  // + 32*XP*2
#define SM_GW  226304
#define SMEM_MMA 228352

__global__ void __launch_bounds__(256) k_mma(const int* __restrict__ lens,
                                             const float* __restrict__ gw,
                                             const float* __restrict__ gb){
    extern __shared__ char sm[];
    const uint32_t smb = smem_u32(sm);
    const int tid = threadIdx.x;
    const int wid = tid >> 5, lane = tid & 31;
    const int t0 = blockIdx.x * 128;
    const int hb = blockIdx.y;
    const int h = hb >> 5, b = hb & 31;
    const int gid = lane >> 2, tig = lane & 3;

    const int len = lens[b];
    const int p = 25 * (h + 1);
    const int ksz = 2 * p + 1;
    const float invlen = 1.0f / (float)len;

    // ---- prefetch W chunk 0 first (overlaps with X fill) ----
    for (int i = tid; i < 32 * 72; i += 256){
        int r = i / 72, g = i % 72;
        cp16(smb + SM_W0 + r * (XP * 2) + g * 16,
             &g_wt4[((size_t)(h * Kk + r) * KEXT) / 8 + g]);
    }
    cp_commit();

    // ---- fill X: 128 rows x 72 uint4; g<64 from enc bf16, g>=64 conv coefs on-the-fly ----
    for (int i = tid; i < 128 * 72; i += 256){
        int r = i / 72, g = i % 72;
        int t = t0 + r;
        uint4 v = make_uint4(0u, 0u, 0u, 0u);
        if (t < Tt){
            if (g < 64){
                v = g_encbf4[(size_t)(b * Tt + t) * 64 + g];
            } else {
                int jlo = p - t;        if (jlo < 0)   jlo = 0;
                int jhi = len - t + p;  if (jhi > ksz) jhi = ksz;
                if (jhi > jlo){
                    int c = (g - 64) * 8;
                    float4 hi0 = *(const float4*)&g_prefixT[h][jhi][c];
                    float4 hi1 = *(const float4*)&g_prefixT[h][jhi][c + 4];
                    float4 lo0 = *(const float4*)&g_prefixT[h][jlo][c];
                    float4 lo1 = *(const float4*)&g_prefixT[h][jlo][c + 4];
                    __nv_bfloat162 p0 = __floats2bfloat162_rn(invlen * (hi0.x - lo0.x),
                                                              invlen * (hi0.y - lo0.y));
                    __nv_bfloat162 p1 = __floats2bfloat162_rn(invlen * (hi0.z - lo0.z),
                                                              invlen * (hi0.w - lo0.w));
                    __nv_bfloat162 p2 = __floats2bfloat162_rn(invlen * (hi1.x - lo1.x),
                                                              invlen * (hi1.y - lo1.y));
                    __nv_bfloat162 p3 = __floats2bfloat162_rn(invlen * (hi1.z - lo1.z),
                                                              invlen * (hi1.w - lo1.w));
                    v.x = *(uint32_t*)&p0; v.y = *(uint32_t*)&p1;
                    v.z = *(uint32_t*)&p2; v.w = *(uint32_t*)&p3;
                }
            }
        }
        *(uint4*)(sm + SM_X + r * (XP * 2) + g * 16) = v;
    }
    for (int i = tid; i < 512; i += 256){
        ((float*)(sm + SM_Q))[i]  = g_q[h][b][i];
        ((float*)(sm + SM_GW))[i] = gw[h * Kk + i];
    }

    // ldmatrix lane address bases
    const uint32_t aBase = smb + SM_X
        + (uint32_t)(wid * 16 + (lane & 7) + ((lane >> 3) & 1) * 8) * (XP * 2)
        + (uint32_t)(lane >> 4) * 16;
    const uint32_t bOff = (uint32_t)((lane & 7) + (lane >> 4) * 8) * (XP * 2)
                        + (uint32_t)((lane >> 3) & 1) * 16;

    float epart0 = 0.f, epart1 = 0.f;      // rows wid*16+gid, +8
    const float* qs = (const float*)(sm + SM_Q);
    const float* gs = (const float*)(sm + SM_GW);

    for (int s = 0; s < 16; ++s){
        const uint32_t wCur = (s & 1) ? (smb + SM_W1) : (smb + SM_W0);
        const uint32_t wNxt = (s & 1) ? (smb + SM_W0) : (smb + SM_W1);

        cp_wait0();
        __syncthreads();                    // chunk s resident; prior readers of wNxt done

        if (s < 15){
            for (int i = tid; i < 32 * 72; i += 256){
                int r = i / 72, g = i % 72;
                cp16(wNxt + r * (XP * 2) + g * 16,
                     &g_wt4[((size_t)(h * Kk + (s + 1) * 32 + r) * KEXT) / 8 + g]);
            }
            cp_commit();
        }

        float acc[16];
        #pragma unroll
        for (int i = 0; i < 16; ++i) acc[i] = 0.f;

        #pragma unroll 4
        for (int ks = 0; ks < 36; ++ks){
            uint32_t a0, a1, a2, a3;
            ldsm4(a0, a1, a2, a3, aBase + ks * 32);
            #pragma unroll
            for (int pp = 0; pp < 2; ++pp){
                uint32_t b0, b1, b2, b3;
                ldsm4(b0, b1, b2, b3, wCur + (uint32_t)pp * 16 * (XP * 2) + bOff + ks * 32);
                mma_bf16(acc[pp*8+0], acc[pp*8+1], acc[pp*8+2], acc[pp*8+3], a0, a1, a2, a3, b0, b1);
                mma_bf16(acc[pp*8+4], acc[pp*8+5], acc[pp*8+6], acc[pp*8+7], a0, a1, a2, a3, b2, b3);
            }
        }

        // epilogue for this 32-col chunk
        #pragma unroll
        for (int j = 0; j < 4; ++j){
            int n = s * 32 + j * 8 + tig * 2;
            float2 qv = *(const float2*)(qs + n);
            float2 gv = *(const float2*)(gs + n);
            epart0 += gv.x * tanhfast(acc[j*4+0] + qv.x) + gv.y * tanhfast(acc[j*4+1] + qv.y);
            epart1 += gv.x * tanhfast(acc[j*4+2] + qv.x) + gv.y * tanhfast(acc[j*4+3] + qv.y);
        }
        __syncthreads();                    // all warps done reading wCur before s+1 overwrites it
    }

    // reduce over tig (4 lanes per row) via xor shuffles within quad
    #pragma unroll
    for (int off = 1; off < 4; off <<= 1){
        epart0 += __shfl_xor_sync(0xffffffffu, epart0, off);
        epart1 += __shfl_xor_sync(0xffffffffu, epart1, off);
    }
    if (tig == 0){
        float gbv = gb[h];
        int r0 = wid * 16 + gid;
        int t_a = t0 + r0, t_b = t0 + r0 + 8;
        if (t_a < Tt) g_e[h][b][t_a] = epart0 + gbv;
        if (t_b < Tt) g_e[h][b][t_b] = epart1 + gbv;
    }
}

// ---------------- masked softmax over t ----------------
__global__ void k_softmax(const int* __restrict__ lens, float* __restrict__ out){
    __shared__ float s[Tt];
    __shared__ float red[33];
    int h = blockIdx.x >> 5, b = blockIdx.x & 31;
    int tid = threadIdx.x;
    int lane = tid & 31, warp = tid >> 5;
    int len = lens[b];

    float m = -1e30f;
    for (int t = tid; t < len; t += 256){
        float v = SCALING_F * g_e[h][b][t];
        s[t] = v;
        m = fmaxf(m, v);
    }
    #pragma unroll
    for (int off = 16; off; off >>= 1) m = fmaxf(m, __shfl_xor_sync(0xffffffffu, m, off));
    if (lane == 0) red[warp] = m;
    __syncthreads();
    if (tid == 0){
        float v = red[0];
        #pragma unroll
        for (int i = 1; i < 8; ++i) v = fmaxf(v, red[i]);
        red[32] = v;
    }
    __syncthreads();
    float M = red[32];

    float sum = 0.f;
    for (int t = tid; t < len; t += 256){
        float ev = __expf(s[t] - M);
        s[t] = ev;
        sum += ev;
    }
    #pragma unroll
    for (int off = 16; off; off >>= 1) sum += __shfl_xor_sync(0xffffffffu, sum, off);
    if (lane == 0) red[warp] = sum;
    __syncthreads();
    if (tid == 0){
        float v = 0.f;
        #pragma unroll
        for (int i = 0; i < 8; ++i) v += red[i];
        red[32] = v;
    }
    __syncthreads();
    float inv = 1.0f / red[32];

    size_t base = (size_t)(h * Bb + b) * Tt;
    for (int t = tid; t < Tt; t += 256){
        float w = (t < len) ? s[t] * inv : 0.f;
        g_w[h][b][t] = w;
        out[Bb * Ep + base + t] = w;
    }
}

// ---------------- wenc phase 1: t-segment partials (deterministic) ----------------
__global__ void k_wenc1(const float* __restrict__ enc, const int* __restrict__ lens){
    int seg = blockIdx.x, b = blockIdx.y;
    int e = threadIdx.x;
    int len = lens[b];
    int tstart = seg * SEGLEN;
    int tend = min(tstart + SEGLEN, len);
    int nt = tend - tstart; if (nt < 0) nt = 0;
    __shared__ float ws[Hh][SEGLEN];
    for (int i = e; i < Hh * SEGLEN; i += 512){
        int hh = i / SEGLEN, tt = i % SEGLEN;
        ws[hh][tt] = (tt < nt) ? g_w[hh][b][tstart + tt] : 0.f;
    }
    __syncthreads();
    float a0 = 0.f, a1 = 0.f, a2 = 0.f, a3 = 0.f;
    for (int tt = 0; tt < nt; ++tt){
        float x = enc[((size_t)b * Tt + (tstart + tt)) * Ep + e];
        a0 += ws[0][tt] * x; a1 += ws[1][tt] * x;
        a2 += ws[2][tt] * x; a3 += ws[3][tt] * x;
    }
    g_wpart[seg][0][b][e] = a0; g_wpart[seg][1][b][e] = a1;
    g_wpart[seg][2][b][e] = a2; g_wpart[seg][3][b][e] = a3;
}

// ---------------- wenc phase 2: reduce segments ----------------
__global__ void k_wenc2(){
    int b = blockIdx.x;
    int e = threadIdx.x;
    #pragma unroll
    for (int hh = 0; hh < Hh; ++hh){
        float a = 0.f;
        #pragma unroll
        for (int s = 0; s < NSEG; ++s) a += g_wpart[s][hh][b][e];
        g_wenc[hh][b][e] = a;
    }
}

// ---------------- ctx = wenc @ Wv ----------------
__global__ void k_ctx(const float* __restrict__ Wv){
    int h = blockIdx.x >> 5, b = blockIdx.x & 31;
    int v = threadIdx.x;
    __shared__ float xr[Ep];
    xr[v] = g_wenc[h][b][v];
    __syncthreads();
    float acc = 0.f;
    #pragma unroll 8
    for (int e = 0; e < Ep; ++e)
        acc += xr[e] * Wv[((size_t)(h * Ep + e)) * Vv + v];
    g_ctx[b][h * Vv + v] = acc;
}

// ---------------- c = concat(ctx) @ Wo ----------------
__global__ void k_out(const float* __restrict__ Wo, float* __restrict__ out){
    int b = blockIdx.x;
    int n = threadIdx.x;
    __shared__ float cr[Hh * Vv];
    for (int i = n; i < Hh * Vv; i += 512) cr[i] = g_ctx[b][i];
    __syncthreads();
    float acc = 0.f;
    #pragma unroll 8
    for (int j = 0; j < Hh * Vv; ++j)
        acc += cr[j] * Wo[(size_t)j * Ep + n];
    out[b * Ep + n] = acc;
}

// ---------------- launch ----------------
extern "C" void kernel_launch(void* const* d_in, const int* in_sizes, int n_in,
                              void* d_out, int out_size) {
    const float* enc   = (const float*)d_in[0];
    const int*   lens  = (const int*)  d_in[1];
    const float* dec_z = (const float*)d_in[2];
    const float* Wq    = (const float*)d_in[3];
    const float* bq    = (const float*)d_in[4];
    const float* Wk    = (const float*)d_in[5];
    const float* Wv    = (const float*)d_in[6];
    const float* gw    = (const float*)d_in[7];
    const float* gb    = (const float*)d_in[8];
    const float* Watt  = (const float*)d_in[9];
    const float* Wo    = (const float*)d_in[10];
    const float* cw0   = (const float*)d_in[11];
    const float* cw1   = (const float*)d_in[12];
    const float* cw2   = (const float*)d_in[13];
    const float* cw3   = (const float*)d_in[14];
    float* out = (float*)d_out;

    cudaFuncSetAttribute(k_mma, cudaFuncAttributeMaxDynamicSharedMemorySize, SMEM_MMA);

    k_prep_enc<<<(Bb * Tt * Ep / 8 + 255) / 256, 256>>>(enc);
    k_prep_w<<<(Hh * Kk * KEXT + 1023) / 1024, 1024>>>(Wk, Watt);
    k_qp<<<Hh * Bb + 1, 512>>>(dec_z, Wq, bq, cw0, cw1, cw2, cw3);
    k_mma<<<dim3((Tt + 127) / 128, Hh * Bb), 256, SMEM_MMA>>>(lens, gw, gb);
    k_softmax<<<Hh * Bb, 256>>>(lens, out);
    k_wenc1<<<dim3(NSEG, Bb), 512>>>(enc, lens);
    k_wenc2<<<Bb, 512>>>();
    k_ctx<<<Hh * Bb, 512>>>(Wv);
    k_out<<<Bb, 512>>>(Wo, out);
}